// round 3
// baseline (speedup 1.0000x reference)
#include <cuda_runtime.h>
#include <cstdint>

// Problem constants
#define HN   4
#define BN   2
#define CN   64
#define TN   2048
#define FN   64
#define HIDN 4
#define VDN  16
#define HBN  8       // H*B
#define DQK  256     // HID*F
#define DV   1024    // VD*F
#define EPSV 1e-5f

// Scratch (static device globals; allocation APIs are banned)
__device__ float g_Q [(size_t)HBN * TN * DQK];   //  16.8 MB (tf32-rounded, pre-scaled)
__device__ float g_Kt[(size_t)HBN * DQK * TN];   //  16.8 MB (tf32-rounded, d-major)
__device__ float g_V [(size_t)HBN * TN * DV];    //  67.1 MB (tf32-rounded)
__device__ float g_S [(size_t)HBN * TN * TN];    // 134.2 MB (fp32 logits -> tf32 probs)
__device__ float g_O [(size_t)HBN * TN * DV];    //  67.1 MB (fp32)

__device__ __forceinline__ float warpSum(float v) {
    #pragma unroll
    for (int s = 16; s > 0; s >>= 1) v += __shfl_down_sync(0xffffffffu, v, s);
    return v;
}
__device__ __forceinline__ float warpMax(float v) {
    #pragma unroll
    for (int s = 16; s > 0; s >>= 1) v = fmaxf(v, __shfl_down_sync(0xffffffffu, v, s));
    return v;
}
__device__ __forceinline__ uint32_t f2tf32(float x) {
    uint32_t u;
    asm("cvt.rna.tf32.f32 %0, %1;" : "=r"(u) : "f"(x));
    return u;
}
__device__ __forceinline__ float tf32f(float x) { return __uint_as_float(f2tf32(x)); }

__device__ __forceinline__ void cpasync16(uint32_t dst, const void* src) {
    asm volatile("cp.async.cg.shared.global [%0], [%1], 16;" :: "r"(dst), "l"(src));
}

#define MMA_TF32(d, a, b)                                                     \
    asm volatile(                                                             \
        "mma.sync.aligned.m16n8k8.row.col.f32.tf32.tf32.f32 "                 \
        "{%0,%1,%2,%3}, {%4,%5,%6,%7}, {%8,%9}, {%0,%1,%2,%3};"               \
        : "+f"((d)[0]), "+f"((d)[1]), "+f"((d)[2]), "+f"((d)[3])              \
        : "r"((a)[0]), "r"((a)[1]), "r"((a)[2]), "r"((a)[3]),                 \
          "r"((b)[0]), "r"((b)[1]))

// ---------------------------------------------------------------------------
// Kernel 1: fused QKV projection + PReLU + LayerNorm over (chan,freq)
// ---------------------------------------------------------------------------
__global__ __launch_bounds__(256) void qkv_kernel(
    const float* __restrict__ x,
    const float* __restrict__ Wq, const float* __restrict__ bq, const float* __restrict__ aq,
    const float* __restrict__ gq, const float* __restrict__ betq,
    const float* __restrict__ Wk, const float* __restrict__ bk, const float* __restrict__ ak,
    const float* __restrict__ gk, const float* __restrict__ betk,
    const float* __restrict__ Wv, const float* __restrict__ bv, const float* __restrict__ av,
    const float* __restrict__ gv, const float* __restrict__ betv)
{
    __shared__ float xs[CN][FN];
    __shared__ float wt[HN][CN][24];
    __shared__ float rbuf[8][24];
    __shared__ float fin[24];

    const int t = blockIdx.x, b = blockIdx.y;
    const int tid = threadIdx.x;

    for (int i = tid; i < CN * FN; i += 256) {
        int c = i >> 6, f = i & 63;
        xs[c][f] = x[(((size_t)b * CN + c) * TN + t) * FN + f];
    }
    for (int i = tid; i < HN * CN * 24; i += 256) {
        int og = i / (CN * 24);
        int c  = (i / 24) % CN;
        int w  = i % 24;
        float val;
        if (w < 4)      val = Wq[(w * HIDN + og) * CN + c];
        else if (w < 8) val = Wk[((w - 4) * HIDN + og) * CN + c];
        else {
            int j = (w - 8) >> 2, m = (w - 8) & 3;
            val = Wv[(j * VDN + og * 4 + m) * CN + c];
        }
        wt[og][c][w] = val;
    }
    __syncthreads();

    const int f = tid & 63, og = tid >> 6;

    float accq[4], acck[4], accv[16];
    #pragma unroll
    for (int j = 0; j < 4; j++) { accq[j] = bq[j * HIDN + og]; acck[j] = bk[j * HIDN + og]; }
    #pragma unroll
    for (int j = 0; j < 4; j++)
        #pragma unroll
        for (int m = 0; m < 4; m++) accv[j * 4 + m] = bv[j * VDN + og * 4 + m];

    #pragma unroll 4
    for (int c = 0; c < CN; c++) {
        float xv = xs[c][f];
        const float4* wp4 = (const float4*)&wt[og][c][0];
        float w[24];
        *(float4*)&w[0]  = wp4[0];
        *(float4*)&w[4]  = wp4[1];
        *(float4*)&w[8]  = wp4[2];
        *(float4*)&w[12] = wp4[3];
        *(float4*)&w[16] = wp4[4];
        *(float4*)&w[20] = wp4[5];
        #pragma unroll
        for (int q = 0; q < 4; q++)  accq[q] = fmaf(w[q],      xv, accq[q]);
        #pragma unroll
        for (int q = 0; q < 4; q++)  acck[q] = fmaf(w[4 + q],  xv, acck[q]);
        #pragma unroll
        for (int q = 0; q < 16; q++) accv[q] = fmaf(w[8 + q],  xv, accv[q]);
    }

    // PReLU
    #pragma unroll
    for (int j = 0; j < 4; j++) {
        float a1 = aq[j], a2 = ak[j];
        accq[j] = accq[j] >= 0.f ? accq[j] : a1 * accq[j];
        acck[j] = acck[j] >= 0.f ? acck[j] : a2 * acck[j];
    }
    #pragma unroll
    for (int j = 0; j < 4; j++) {
        float a3 = av[j];
        #pragma unroll
        for (int m = 0; m < 4; m++) {
            float v = accv[j * 4 + m];
            accv[j * 4 + m] = v >= 0.f ? v : a3 * v;
        }
    }

    // per-head mean/var reductions
    float s[12], sq[12];
    #pragma unroll
    for (int j = 0; j < 4; j++) {
        s[j] = accq[j];       sq[j] = accq[j] * accq[j];
        s[4 + j] = acck[j];   sq[4 + j] = acck[j] * acck[j];
        float ps = 0.f, pq = 0.f;
        #pragma unroll
        for (int m = 0; m < 4; m++) { float v = accv[j * 4 + m]; ps += v; pq += v * v; }
        s[8 + j] = ps; sq[8 + j] = pq;
    }
    int lane = tid & 31, wid = tid >> 5;
    #pragma unroll
    for (int q = 0; q < 12; q++) {
        float a = warpSum(s[q]);
        float b2 = warpSum(sq[q]);
        if (lane == 0) { rbuf[wid][q] = a; rbuf[wid][12 + q] = b2; }
    }
    __syncthreads();
    if (tid < 24) {
        float a = 0.f;
        #pragma unroll
        for (int w2 = 0; w2 < 8; w2++) a += rbuf[w2][tid];
        fin[tid] = a;
    }
    __syncthreads();

    const float QSCALE = 0.0625f;  // 1/sqrt(256), folded into Q

    #pragma unroll
    for (int j = 0; j < 4; j++) {
        float mu = fin[j] * (1.f / 256.f);
        float var = fin[12 + j] * (1.f / 256.f) - mu * mu;
        float rs = rsqrtf(var + EPSV);
        int gi = (j * HIDN + og) * FN + f;
        float qv = ((accq[j] - mu) * rs * gq[gi] + betq[gi]) * QSCALE;
        g_Q[(((size_t)(j * BN + b)) * TN + t) * DQK + og * FN + f] = tf32f(qv);

        float muk = fin[4 + j] * (1.f / 256.f);
        float vark = fin[16 + j] * (1.f / 256.f) - muk * muk;
        float rsk = rsqrtf(vark + EPSV);
        float kv = (acck[j] - muk) * rsk * gk[gi] + betk[gi];
        g_Kt[(((size_t)(j * BN + b)) * DQK + og * FN + f) * TN + t] = tf32f(kv);
    }
    #pragma unroll
    for (int j = 0; j < 4; j++) {
        float mu = fin[8 + j] * (1.f / 1024.f);
        float var = fin[20 + j] * (1.f / 1024.f) - mu * mu;
        float rs = rsqrtf(var + EPSV);
        #pragma unroll
        for (int m = 0; m < 4; m++) {
            int vd = og * 4 + m;
            int gi = (j * VDN + vd) * FN + f;
            float vv = (accv[j * 4 + m] - mu) * rs * gv[gi] + betv[gi];
            g_V[(((size_t)(j * BN + b)) * TN + t) * DV + vd * FN + f] = tf32f(vv);
        }
    }
}

// ---------------------------------------------------------------------------
// Kernel 2/4: TF32 tensor-core GEMM v2.
//   CTA tile 128x128, BK=32, 3-stage cp.async pipeline, 105KB dynamic smem.
//   128 threads = 4 warps, warp tile 64x64 (2x2 warp grid), m16n8k8 tf32 mma.
// MODE 0: S = Q * Kt   (M=T, N=T,  K=DQK)
// MODE 1: O = P * V    (M=T, N=DV, K=T)
// ---------------------------------------------------------------------------
#define ASTR 36
#define BSTR 136
#define A_STAGE_F (128 * ASTR)          // 4608 floats
#define B_STAGE_F (32 * BSTR)           // 4352 floats
#define B_BASE_F  (3 * A_STAGE_F)       // 13824 floats
#define GEMM_SMEM_BYTES ((B_BASE_F + 3 * B_STAGE_F) * 4)   // 107520 B

template<int MODE>
__global__ __launch_bounds__(128, 2) void gemm_tc()
{
    constexpr int LDA  = (MODE == 0) ? DQK : TN;
    constexpr int LDB  = (MODE == 0) ? TN  : DV;
    constexpr int LDC  = (MODE == 0) ? TN  : DV;
    constexpr int KTOT = (MODE == 0) ? DQK : TN;
    constexpr int NT   = KTOT / 32;

    extern __shared__ float sm[];

    const int hb = blockIdx.z;
    const float* A = (MODE == 0 ? g_Q : g_S)
                   + (size_t)hb * TN * LDA + (size_t)blockIdx.y * 128 * LDA;
    const float* B = (MODE == 0 ? g_Kt : g_V)
                   + (size_t)hb * KTOT * LDB + blockIdx.x * 128;
    float* C = (MODE == 0 ? g_S : g_O)
             + (size_t)hb * TN * LDC + (size_t)blockIdx.y * 128 * LDC + blockIdx.x * 128;

    const int tid = threadIdx.x;
    const int lane = tid & 31, w = tid >> 5;
    const int wm = (w & 1) * 64, wn = (w >> 1) * 64;
    const int r = lane >> 2, cq = lane & 3;

    // loaders: A -> one row (32 floats = 8 x float4) per thread
    const int arow = tid;
    // B: brow in 0..7, 4 rows (brow + 8p), 2 float4 each
    const int brow = tid >> 4, bnseg = (tid & 15) * 8;

    const uint32_t smBase = (uint32_t)__cvta_generic_to_shared(sm);

    auto issue = [&](int it, int buf) {
        const float* ap = A + (size_t)arow * LDA + it * 32;
        uint32_t ad = smBase + (uint32_t)(buf * A_STAGE_F + arow * ASTR) * 4u;
        #pragma unroll
        for (int j = 0; j < 8; j++)
            cpasync16(ad + j * 16u, ap + j * 4);
        #pragma unroll
        for (int p = 0; p < 4; p++) {
            const float* bp = B + (size_t)(it * 32 + brow + p * 8) * LDB + bnseg;
            uint32_t bd = smBase +
                (uint32_t)(B_BASE_F + buf * B_STAGE_F + (brow + p * 8) * BSTR + bnseg) * 4u;
            cpasync16(bd, bp);
            cpasync16(bd + 16u, bp + 4);
        }
        asm volatile("cp.async.commit_group;");
    };

    float acc[4][8][4];
    #pragma unroll
    for (int mi = 0; mi < 4; mi++)
        #pragma unroll
        for (int ni = 0; ni < 8; ni++)
            #pragma unroll
            for (int q = 0; q < 4; q++) acc[mi][ni][q] = 0.f;

    issue(0, 0);
    issue(1, 1);

    for (int it = 0; it < NT; ++it) {
        if (it == NT - 1) asm volatile("cp.async.wait_group 0;");
        else              asm volatile("cp.async.wait_group 1;");
        __syncthreads();

        if (it + 2 < NT) issue(it + 2, (it + 2) % 3);

        const float* Asb = sm + (it % 3) * A_STAGE_F;
        const float* Bsb = sm + B_BASE_F + (it % 3) * B_STAGE_F;

        #pragma unroll
        for (int kk = 0; kk < 32; kk += 8) {
            uint32_t af[4][4];
            #pragma unroll
            for (int mi = 0; mi < 4; mi++) {
                const int mrow = wm + mi * 16;
                af[mi][0] = __float_as_uint(Asb[(mrow + r)     * ASTR + kk + cq]);
                af[mi][1] = __float_as_uint(Asb[(mrow + r + 8) * ASTR + kk + cq]);
                af[mi][2] = __float_as_uint(Asb[(mrow + r)     * ASTR + kk + cq + 4]);
                af[mi][3] = __float_as_uint(Asb[(mrow + r + 8) * ASTR + kk + cq + 4]);
            }
            uint32_t bf[8][2];
            #pragma unroll
            for (int ni = 0; ni < 8; ni++) {
                const int ncol = wn + ni * 8 + r;
                bf[ni][0] = __float_as_uint(Bsb[(kk + cq)     * BSTR + ncol]);
                bf[ni][1] = __float_as_uint(Bsb[(kk + cq + 4) * BSTR + ncol]);
            }
            #pragma unroll
            for (int mi = 0; mi < 4; mi++)
                #pragma unroll
                for (int ni = 0; ni < 8; ni++)
                    MMA_TF32(acc[mi][ni], af[mi], bf[ni]);
        }
        __syncthreads();
    }

    #pragma unroll
    for (int mi = 0; mi < 4; mi++) {
        const int row0 = wm + mi * 16 + r;
        #pragma unroll
        for (int ni = 0; ni < 8; ni++) {
            const int col = wn + ni * 8 + cq * 2;
            float2 v0 = make_float2(acc[mi][ni][0], acc[mi][ni][1]);
            float2 v1 = make_float2(acc[mi][ni][2], acc[mi][ni][3]);
            *(float2*)&C[(size_t)row0 * LDC + col]       = v0;
            *(float2*)&C[(size_t)(row0 + 8) * LDC + col] = v1;
        }
    }
}

// ---------------------------------------------------------------------------
// Kernel 3: row softmax (one read + one write), output rounded to tf32
// ---------------------------------------------------------------------------
__global__ __launch_bounds__(256) void softmax_kernel()
{
    const size_t row = blockIdx.x;
    float* p = g_S + row * TN;
    const int tid = threadIdx.x;
    const int lane = tid & 31, wid = tid >> 5;
    __shared__ float red[8];
    __shared__ float bmax, bsum;

    float v[8];
    float m = -1e30f;
    #pragma unroll
    for (int j = 0; j < 8; j++) { v[j] = p[tid + j * 256]; m = fmaxf(m, v[j]); }
    m = warpMax(m);
    if (lane == 0) red[wid] = m;
    __syncthreads();
    if (tid == 0) {
        float mm = red[0];
        #pragma unroll
        for (int w = 1; w < 8; w++) mm = fmaxf(mm, red[w]);
        bmax = mm;
    }
    __syncthreads();
    float M = bmax;
    float sum = 0.f;
    #pragma unroll
    for (int j = 0; j < 8; j++) { v[j] = __expf(v[j] - M); sum += v[j]; }
    sum = warpSum(sum);
    if (lane == 0) red[wid] = sum;
    __syncthreads();
    if (tid == 0) {
        float ss = 0.f;
        #pragma unroll
        for (int w = 0; w < 8; w++) ss += red[w];
        bsum = ss;
    }
    __syncthreads();
    float r = 1.f / bsum;
    #pragma unroll
    for (int j = 0; j < 8; j++) p[tid + j * 256] = tf32f(v[j] * r);
}

// ---------------------------------------------------------------------------
// Kernel 5: out = LN(PReLU(Wp @ concat(O) + bp)) + x   per (b,t)
// ---------------------------------------------------------------------------
__global__ __launch_bounds__(256) void outproj_kernel(
    const float* __restrict__ x, const float* __restrict__ Wp, const float* __restrict__ bp,
    const float* __restrict__ ap, const float* __restrict__ gp, const float* __restrict__ betp,
    float* __restrict__ out)
{
    __shared__ float Oc[CN][FN];
    __shared__ float wt[4][CN][16];
    __shared__ float rbuf[8][2];
    __shared__ float fin2[2];

    const int t = blockIdx.x, b = blockIdx.y;
    const int tid = threadIdx.x;

    for (int i = tid; i < CN * FN; i += 256) {
        int c = i >> 6, f = i & 63;
        int h = c >> 4, vd = c & 15;
        Oc[c][f] = g_O[(((size_t)(h * BN + b)) * TN + t) * DV + vd * FN + f];
    }
    for (int i = tid; i < 4 * CN * 16; i += 256) {
        int og = i / (CN * 16), c = (i >> 4) % CN, m = i & 15;
        wt[og][c][m] = Wp[(og * 16 + m) * CN + c];
    }
    __syncthreads();

    const int f = tid & 63, og = tid >> 6;
    float acc[16];
    #pragma unroll
    for (int m = 0; m < 16; m++) acc[m] = bp[og * 16 + m];

    #pragma unroll 4
    for (int c = 0; c < CN; c++) {
        float xv = Oc[c][f];
        const float4* wp4 = (const float4*)&wt[og][c][0];
        float w[16];
        *(float4*)&w[0]  = wp4[0];
        *(float4*)&w[4]  = wp4[1];
        *(float4*)&w[8]  = wp4[2];
        *(float4*)&w[12] = wp4[3];
        #pragma unroll
        for (int m = 0; m < 16; m++) acc[m] = fmaf(w[m], xv, acc[m]);
    }

    float a = ap[0];
    float ps = 0.f, pq = 0.f;
    #pragma unroll
    for (int m = 0; m < 16; m++) {
        float v = acc[m];
        v = v >= 0.f ? v : a * v;
        acc[m] = v;
        ps += v; pq += v * v;
    }
    int lane = tid & 31, wid = tid >> 5;
    ps = warpSum(ps); pq = warpSum(pq);
    if (lane == 0) { rbuf[wid][0] = ps; rbuf[wid][1] = pq; }
    __syncthreads();
    if (tid == 0) {
        float s0 = 0.f, s1 = 0.f;
        #pragma unroll
        for (int w = 0; w < 8; w++) { s0 += rbuf[w][0]; s1 += rbuf[w][1]; }
        fin2[0] = s0; fin2[1] = s1;
    }
    __syncthreads();
    float mu = fin2[0] * (1.f / 4096.f);
    float var = fin2[1] * (1.f / 4096.f) - mu * mu;
    float rs = rsqrtf(var + EPSV);

    #pragma unroll
    for (int m = 0; m < 16; m++) {
        int o = og * 16 + m;
        float v = (acc[m] - mu) * rs * gp[o * FN + f] + betp[o * FN + f];
        size_t idx = (((size_t)b * CN + o) * TN + t) * FN + f;
        out[idx] = v + x[idx];
    }
}

// ---------------------------------------------------------------------------
extern "C" void kernel_launch(void* const* d_in, const int* in_sizes, int n_in,
                              void* d_out, int out_size)
{
    const float* x    = (const float*)d_in[0];
    const float* Wq   = (const float*)d_in[1];
    const float* bq   = (const float*)d_in[2];
    const float* aq   = (const float*)d_in[3];
    const float* gq   = (const float*)d_in[4];
    const float* betq = (const float*)d_in[5];
    const float* Wk   = (const float*)d_in[6];
    const float* bk   = (const float*)d_in[7];
    const float* ak   = (const float*)d_in[8];
    const float* gk   = (const float*)d_in[9];
    const float* betk = (const float*)d_in[10];
    const float* Wv   = (const float*)d_in[11];
    const float* bv   = (const float*)d_in[12];
    const float* av   = (const float*)d_in[13];
    const float* gv   = (const float*)d_in[14];
    const float* betv = (const float*)d_in[15];
    const float* Wp   = (const float*)d_in[16];
    const float* bp   = (const float*)d_in[17];
    const float* ap   = (const float*)d_in[18];
    const float* gp   = (const float*)d_in[19];
    const float* betp = (const float*)d_in[20];
    float* out = (float*)d_out;

    cudaFuncSetAttribute(gemm_tc<0>, cudaFuncAttributeMaxDynamicSharedMemorySize,
                         GEMM_SMEM_BYTES);
    cudaFuncSetAttribute(gemm_tc<1>, cudaFuncAttributeMaxDynamicSharedMemorySize,
                         GEMM_SMEM_BYTES);

    qkv_kernel<<<dim3(TN, BN), 256>>>(x, Wq, bq, aq, gq, betq,
                                      Wk, bk, ak, gk, betk,
                                      Wv, bv, av, gv, betv);
    gemm_tc<0><<<dim3(TN / 128, TN / 128, HBN), 128, GEMM_SMEM_BYTES>>>();
    softmax_kernel<<<HBN * TN, 256>>>();
    gemm_tc<1><<<dim3(DV / 128, TN / 128, HBN), 128, GEMM_SMEM_BYTES>>>();
    outproj_kernel<<<dim3(TN, BN), 256>>>(x, Wp, bp, ap, gp, betp, out);
}

// round 4
// speedup vs baseline: 1.1117x; 1.1117x over previous
#include <cuda_runtime.h>
#include <cstdint>

// Problem constants
#define HN   4
#define BN   2
#define CN   64
#define TN   2048
#define FN   64
#define HIDN 4
#define VDN  16
#define HBN  8       // H*B
#define DQK  256     // HID*F
#define DV   1024    // VD*F
#define EPSV 1e-5f

// Scratch (static device globals; allocation APIs are banned)
__device__ float g_Q [(size_t)HBN * TN * DQK];   //  16.8 MB (tf32-rounded, pre-scaled)
__device__ float g_Kt[(size_t)HBN * DQK * TN];   //  16.8 MB (tf32-rounded, d-major)
__device__ float g_V [(size_t)HBN * TN * DV];    //  67.1 MB (tf32-rounded)
__device__ float g_S [(size_t)HBN * TN * TN];    // 134.2 MB (fp32 logits -> tf32 probs)
__device__ float g_O [(size_t)HBN * TN * DV];    //  67.1 MB (fp32)

__device__ __forceinline__ float warpSum(float v) {
    #pragma unroll
    for (int s = 16; s > 0; s >>= 1) v += __shfl_down_sync(0xffffffffu, v, s);
    return v;
}
__device__ __forceinline__ float warpMax(float v) {
    #pragma unroll
    for (int s = 16; s > 0; s >>= 1) v = fmaxf(v, __shfl_down_sync(0xffffffffu, v, s));
    return v;
}
__device__ __forceinline__ uint32_t f2tf32(float x) {
    uint32_t u;
    asm("cvt.rna.tf32.f32 %0, %1;" : "=r"(u) : "f"(x));
    return u;
}
__device__ __forceinline__ float tf32f(float x) { return __uint_as_float(f2tf32(x)); }

__device__ __forceinline__ void cpasync16(uint32_t dst, const void* src) {
    asm volatile("cp.async.cg.shared.global [%0], [%1], 16;" :: "r"(dst), "l"(src));
}

#define MMA_TF32(d, a, b)                                                     \
    asm volatile(                                                             \
        "mma.sync.aligned.m16n8k8.row.col.f32.tf32.tf32.f32 "                 \
        "{%0,%1,%2,%3}, {%4,%5,%6,%7}, {%8,%9}, {%0,%1,%2,%3};"               \
        : "+f"((d)[0]), "+f"((d)[1]), "+f"((d)[2]), "+f"((d)[3])              \
        : "r"((a)[0]), "r"((a)[1]), "r"((a)[2]), "r"((a)[3]),                 \
          "r"((b)[0]), "r"((b)[1]))

// ---------------------------------------------------------------------------
// Kernel 1: fused QKV projection + PReLU + LayerNorm over (chan,freq)
// ---------------------------------------------------------------------------
__global__ __launch_bounds__(256) void qkv_kernel(
    const float* __restrict__ x,
    const float* __restrict__ Wq, const float* __restrict__ bq, const float* __restrict__ aq,
    const float* __restrict__ gq, const float* __restrict__ betq,
    const float* __restrict__ Wk, const float* __restrict__ bk, const float* __restrict__ ak,
    const float* __restrict__ gk, const float* __restrict__ betk,
    const float* __restrict__ Wv, const float* __restrict__ bv, const float* __restrict__ av,
    const float* __restrict__ gv, const float* __restrict__ betv)
{
    __shared__ float xs[CN][FN];
    __shared__ float wt[HN][CN][24];
    __shared__ float rbuf[8][24];
    __shared__ float fin[24];

    const int t = blockIdx.x, b = blockIdx.y;
    const int tid = threadIdx.x;

    for (int i = tid; i < CN * FN; i += 256) {
        int c = i >> 6, f = i & 63;
        xs[c][f] = x[(((size_t)b * CN + c) * TN + t) * FN + f];
    }
    for (int i = tid; i < HN * CN * 24; i += 256) {
        int og = i / (CN * 24);
        int c  = (i / 24) % CN;
        int w  = i % 24;
        float val;
        if (w < 4)      val = Wq[(w * HIDN + og) * CN + c];
        else if (w < 8) val = Wk[((w - 4) * HIDN + og) * CN + c];
        else {
            int j = (w - 8) >> 2, m = (w - 8) & 3;
            val = Wv[(j * VDN + og * 4 + m) * CN + c];
        }
        wt[og][c][w] = val;
    }
    __syncthreads();

    const int f = tid & 63, og = tid >> 6;

    float accq[4], acck[4], accv[16];
    #pragma unroll
    for (int j = 0; j < 4; j++) { accq[j] = bq[j * HIDN + og]; acck[j] = bk[j * HIDN + og]; }
    #pragma unroll
    for (int j = 0; j < 4; j++)
        #pragma unroll
        for (int m = 0; m < 4; m++) accv[j * 4 + m] = bv[j * VDN + og * 4 + m];

    #pragma unroll 4
    for (int c = 0; c < CN; c++) {
        float xv = xs[c][f];
        const float4* wp4 = (const float4*)&wt[og][c][0];
        float w[24];
        *(float4*)&w[0]  = wp4[0];
        *(float4*)&w[4]  = wp4[1];
        *(float4*)&w[8]  = wp4[2];
        *(float4*)&w[12] = wp4[3];
        *(float4*)&w[16] = wp4[4];
        *(float4*)&w[20] = wp4[5];
        #pragma unroll
        for (int q = 0; q < 4; q++)  accq[q] = fmaf(w[q],      xv, accq[q]);
        #pragma unroll
        for (int q = 0; q < 4; q++)  acck[q] = fmaf(w[4 + q],  xv, acck[q]);
        #pragma unroll
        for (int q = 0; q < 16; q++) accv[q] = fmaf(w[8 + q],  xv, accv[q]);
    }

    // PReLU
    #pragma unroll
    for (int j = 0; j < 4; j++) {
        float a1 = aq[j], a2 = ak[j];
        accq[j] = accq[j] >= 0.f ? accq[j] : a1 * accq[j];
        acck[j] = acck[j] >= 0.f ? acck[j] : a2 * acck[j];
    }
    #pragma unroll
    for (int j = 0; j < 4; j++) {
        float a3 = av[j];
        #pragma unroll
        for (int m = 0; m < 4; m++) {
            float v = accv[j * 4 + m];
            accv[j * 4 + m] = v >= 0.f ? v : a3 * v;
        }
    }

    // per-head mean/var reductions
    float s[12], sq[12];
    #pragma unroll
    for (int j = 0; j < 4; j++) {
        s[j] = accq[j];       sq[j] = accq[j] * accq[j];
        s[4 + j] = acck[j];   sq[4 + j] = acck[j] * acck[j];
        float ps = 0.f, pq = 0.f;
        #pragma unroll
        for (int m = 0; m < 4; m++) { float v = accv[j * 4 + m]; ps += v; pq += v * v; }
        s[8 + j] = ps; sq[8 + j] = pq;
    }
    int lane = tid & 31, wid = tid >> 5;
    #pragma unroll
    for (int q = 0; q < 12; q++) {
        float a = warpSum(s[q]);
        float b2 = warpSum(sq[q]);
        if (lane == 0) { rbuf[wid][q] = a; rbuf[wid][12 + q] = b2; }
    }
    __syncthreads();
    if (tid < 24) {
        float a = 0.f;
        #pragma unroll
        for (int w2 = 0; w2 < 8; w2++) a += rbuf[w2][tid];
        fin[tid] = a;
    }
    __syncthreads();

    const float QSCALE = 0.0625f;  // 1/sqrt(256), folded into Q

    #pragma unroll
    for (int j = 0; j < 4; j++) {
        float mu = fin[j] * (1.f / 256.f);
        float var = fin[12 + j] * (1.f / 256.f) - mu * mu;
        float rs = rsqrtf(var + EPSV);
        int gi = (j * HIDN + og) * FN + f;
        float qv = ((accq[j] - mu) * rs * gq[gi] + betq[gi]) * QSCALE;
        g_Q[(((size_t)(j * BN + b)) * TN + t) * DQK + og * FN + f] = tf32f(qv);

        float muk = fin[4 + j] * (1.f / 256.f);
        float vark = fin[16 + j] * (1.f / 256.f) - muk * muk;
        float rsk = rsqrtf(vark + EPSV);
        float kv = (acck[j] - muk) * rsk * gk[gi] + betk[gi];
        g_Kt[(((size_t)(j * BN + b)) * DQK + og * FN + f) * TN + t] = tf32f(kv);
    }
    #pragma unroll
    for (int j = 0; j < 4; j++) {
        float mu = fin[8 + j] * (1.f / 1024.f);
        float var = fin[20 + j] * (1.f / 1024.f) - mu * mu;
        float rs = rsqrtf(var + EPSV);
        #pragma unroll
        for (int m = 0; m < 4; m++) {
            int vd = og * 4 + m;
            int gi = (j * VDN + vd) * FN + f;
            float vv = (accv[j * 4 + m] - mu) * rs * gv[gi] + betv[gi];
            g_V[(((size_t)(j * BN + b)) * TN + t) * DV + vd * FN + f] = tf32f(vv);
        }
    }
}

// ---------------------------------------------------------------------------
// Kernel 2/4: TF32 tensor-core GEMM v3 (R2 shape + 4-stage pipeline).
//   CTA tile 128x128, BK=16, 256 threads = 8 warps, warp tile 32x64 (4x2),
//   4-stage cp.async pipeline (75.8 KB dynamic smem), 2 CTAs/SM.
// MODE 0: S = Q * Kt   (M=T, N=T,  K=DQK)
// MODE 1: O = P * V    (M=T, N=DV, K=T)
// ---------------------------------------------------------------------------
#define ASTR 20
#define BSTR 136
#define A_STAGE_F (128 * ASTR)          // 2560 floats
#define B_STAGE_F (16 * BSTR)           // 2176 floats
#define B_BASE_F  (4 * A_STAGE_F)       // 10240 floats
#define GEMM_SMEM_BYTES ((B_BASE_F + 4 * B_STAGE_F) * 4)   // 75776 B

template<int MODE>
__global__ __launch_bounds__(256, 2) void gemm_tc()
{
    constexpr int LDA  = (MODE == 0) ? DQK : TN;
    constexpr int LDB  = (MODE == 0) ? TN  : DV;
    constexpr int LDC  = (MODE == 0) ? TN  : DV;
    constexpr int KTOT = (MODE == 0) ? DQK : TN;
    constexpr int NT   = KTOT / 16;

    extern __shared__ float sm[];

    const int hb = blockIdx.z;
    const float* A = (MODE == 0 ? g_Q : g_S)
                   + (size_t)hb * TN * LDA + (size_t)blockIdx.y * 128 * LDA;
    const float* B = (MODE == 0 ? g_Kt : g_V)
                   + (size_t)hb * KTOT * LDB + blockIdx.x * 128;
    float* C = (MODE == 0 ? g_S : g_O)
             + (size_t)hb * TN * LDC + (size_t)blockIdx.y * 128 * LDC + blockIdx.x * 128;

    const int tid = threadIdx.x;
    const int lane = tid & 31, w = tid >> 5;
    const int wm = (w & 3) * 32, wn = (w >> 2) * 64;
    const int r = lane >> 2, cq = lane & 3;

    const int arow = tid >> 1,  akseg = (tid & 1) * 8;   // A: 2 float4 per thread
    const int brow = tid >> 4,  bnseg = (tid & 15) * 8;  // B: 2 float4 per thread

    const uint32_t smBase = (uint32_t)__cvta_generic_to_shared(sm);

    auto issue = [&](int it, int buf) {
        const float* ap = A + (size_t)arow * LDA + it * 16 + akseg;
        uint32_t ad = smBase + (uint32_t)(buf * A_STAGE_F + arow * ASTR + akseg) * 4u;
        cpasync16(ad, ap);
        cpasync16(ad + 16u, ap + 4);
        const float* bp = B + (size_t)(it * 16 + brow) * LDB + bnseg;
        uint32_t bd = smBase + (uint32_t)(B_BASE_F + buf * B_STAGE_F + brow * BSTR + bnseg) * 4u;
        cpasync16(bd, bp);
        cpasync16(bd + 16u, bp + 4);
        asm volatile("cp.async.commit_group;");
    };

    float acc[2][8][4];
    #pragma unroll
    for (int mi = 0; mi < 2; mi++)
        #pragma unroll
        for (int ni = 0; ni < 8; ni++)
            #pragma unroll
            for (int q = 0; q < 4; q++) acc[mi][ni][q] = 0.f;

    issue(0, 0);
    issue(1, 1);
    issue(2, 2);

    for (int it = 0; it < NT; ++it) {
        if (it + 2 < NT)      asm volatile("cp.async.wait_group 2;");
        else if (it + 1 < NT) asm volatile("cp.async.wait_group 1;");
        else                  asm volatile("cp.async.wait_group 0;");
        __syncthreads();

        if (it + 3 < NT) issue(it + 3, (it + 3) & 3);

        const float* Asb = sm + (it & 3) * A_STAGE_F;
        const float* Bsb = sm + B_BASE_F + (it & 3) * B_STAGE_F;

        #pragma unroll
        for (int kk = 0; kk < 16; kk += 8) {
            uint32_t af[2][4];
            #pragma unroll
            for (int mi = 0; mi < 2; mi++) {
                const int mrow = wm + mi * 16;
                af[mi][0] = __float_as_uint(Asb[(mrow + r)     * ASTR + kk + cq]);
                af[mi][1] = __float_as_uint(Asb[(mrow + r + 8) * ASTR + kk + cq]);
                af[mi][2] = __float_as_uint(Asb[(mrow + r)     * ASTR + kk + cq + 4]);
                af[mi][3] = __float_as_uint(Asb[(mrow + r + 8) * ASTR + kk + cq + 4]);
            }
            uint32_t bf[8][2];
            #pragma unroll
            for (int ni = 0; ni < 8; ni++) {
                const int ncol = wn + ni * 8 + r;
                bf[ni][0] = __float_as_uint(Bsb[(kk + cq)     * BSTR + ncol]);
                bf[ni][1] = __float_as_uint(Bsb[(kk + cq + 4) * BSTR + ncol]);
            }
            #pragma unroll
            for (int mi = 0; mi < 2; mi++)
                #pragma unroll
                for (int ni = 0; ni < 8; ni++)
                    MMA_TF32(acc[mi][ni], af[mi], bf[ni]);
        }
        __syncthreads();
    }

    #pragma unroll
    for (int mi = 0; mi < 2; mi++) {
        const int row0 = wm + mi * 16 + r;
        #pragma unroll
        for (int ni = 0; ni < 8; ni++) {
            const int col = wn + ni * 8 + cq * 2;
            float2 v0 = make_float2(acc[mi][ni][0], acc[mi][ni][1]);
            float2 v1 = make_float2(acc[mi][ni][2], acc[mi][ni][3]);
            *(float2*)&C[(size_t)row0 * LDC + col]       = v0;
            *(float2*)&C[(size_t)(row0 + 8) * LDC + col] = v1;
        }
    }
}

// ---------------------------------------------------------------------------
// Kernel 3: row softmax (one read + one write), output rounded to tf32
// ---------------------------------------------------------------------------
__global__ __launch_bounds__(256) void softmax_kernel()
{
    const size_t row = blockIdx.x;
    float* p = g_S + row * TN;
    const int tid = threadIdx.x;
    const int lane = tid & 31, wid = tid >> 5;
    __shared__ float red[8];
    __shared__ float bmax, bsum;

    float v[8];
    float m = -1e30f;
    #pragma unroll
    for (int j = 0; j < 8; j++) { v[j] = p[tid + j * 256]; m = fmaxf(m, v[j]); }
    m = warpMax(m);
    if (lane == 0) red[wid] = m;
    __syncthreads();
    if (tid == 0) {
        float mm = red[0];
        #pragma unroll
        for (int w = 1; w < 8; w++) mm = fmaxf(mm, red[w]);
        bmax = mm;
    }
    __syncthreads();
    float M = bmax;
    float sum = 0.f;
    #pragma unroll
    for (int j = 0; j < 8; j++) { v[j] = __expf(v[j] - M); sum += v[j]; }
    sum = warpSum(sum);
    if (lane == 0) red[wid] = sum;
    __syncthreads();
    if (tid == 0) {
        float ss = 0.f;
        #pragma unroll
        for (int w = 0; w < 8; w++) ss += red[w];
        bsum = ss;
    }
    __syncthreads();
    float r = 1.f / bsum;
    #pragma unroll
    for (int j = 0; j < 8; j++) p[tid + j * 256] = tf32f(v[j] * r);
}

// ---------------------------------------------------------------------------
// Kernel 5: out = LN(PReLU(Wp @ concat(O) + bp)) + x   per (b,t)
// ---------------------------------------------------------------------------
__global__ __launch_bounds__(256) void outproj_kernel(
    const float* __restrict__ x, const float* __restrict__ Wp, const float* __restrict__ bp,
    const float* __restrict__ ap, const float* __restrict__ gp, const float* __restrict__ betp,
    float* __restrict__ out)
{
    __shared__ float Oc[CN][FN];
    __shared__ float wt[4][CN][16];
    __shared__ float rbuf[8][2];
    __shared__ float fin2[2];

    const int t = blockIdx.x, b = blockIdx.y;
    const int tid = threadIdx.x;

    for (int i = tid; i < CN * FN; i += 256) {
        int c = i >> 6, f = i & 63;
        int h = c >> 4, vd = c & 15;
        Oc[c][f] = g_O[(((size_t)(h * BN + b)) * TN + t) * DV + vd * FN + f];
    }
    for (int i = tid; i < 4 * CN * 16; i += 256) {
        int og = i / (CN * 16), c = (i >> 4) % CN, m = i & 15;
        wt[og][c][m] = Wp[(og * 16 + m) * CN + c];
    }
    __syncthreads();

    const int f = tid & 63, og = tid >> 6;
    float acc[16];
    #pragma unroll
    for (int m = 0; m < 16; m++) acc[m] = bp[og * 16 + m];

    #pragma unroll 4
    for (int c = 0; c < CN; c++) {
        float xv = Oc[c][f];
        const float4* wp4 = (const float4*)&wt[og][c][0];
        float w[16];
        *(float4*)&w[0]  = wp4[0];
        *(float4*)&w[4]  = wp4[1];
        *(float4*)&w[8]  = wp4[2];
        *(float4*)&w[12] = wp4[3];
        #pragma unroll
        for (int m = 0; m < 16; m++) acc[m] = fmaf(w[m], xv, acc[m]);
    }

    float a = ap[0];
    float ps = 0.f, pq = 0.f;
    #pragma unroll
    for (int m = 0; m < 16; m++) {
        float v = acc[m];
        v = v >= 0.f ? v : a * v;
        acc[m] = v;
        ps += v; pq += v * v;
    }
    int lane = tid & 31, wid = tid >> 5;
    ps = warpSum(ps); pq = warpSum(pq);
    if (lane == 0) { rbuf[wid][0] = ps; rbuf[wid][1] = pq; }
    __syncthreads();
    if (tid == 0) {
        float s0 = 0.f, s1 = 0.f;
        #pragma unroll
        for (int w = 0; w < 8; w++) { s0 += rbuf[w][0]; s1 += rbuf[w][1]; }
        fin2[0] = s0; fin2[1] = s1;
    }
    __syncthreads();
    float mu = fin2[0] * (1.f / 4096.f);
    float var = fin2[1] * (1.f / 4096.f) - mu * mu;
    float rs = rsqrtf(var + EPSV);

    #pragma unroll
    for (int m = 0; m < 16; m++) {
        int o = og * 16 + m;
        float v = (acc[m] - mu) * rs * gp[o * FN + f] + betp[o * FN + f];
        size_t idx = (((size_t)b * CN + o) * TN + t) * FN + f;
        out[idx] = v + x[idx];
    }
}

// ---------------------------------------------------------------------------
extern "C" void kernel_launch(void* const* d_in, const int* in_sizes, int n_in,
                              void* d_out, int out_size)
{
    const float* x    = (const float*)d_in[0];
    const float* Wq   = (const float*)d_in[1];
    const float* bq   = (const float*)d_in[2];
    const float* aq   = (const float*)d_in[3];
    const float* gq   = (const float*)d_in[4];
    const float* betq = (const float*)d_in[5];
    const float* Wk   = (const float*)d_in[6];
    const float* bk   = (const float*)d_in[7];
    const float* ak   = (const float*)d_in[8];
    const float* gk   = (const float*)d_in[9];
    const float* betk = (const float*)d_in[10];
    const float* Wv   = (const float*)d_in[11];
    const float* bv   = (const float*)d_in[12];
    const float* av   = (const float*)d_in[13];
    const float* gv   = (const float*)d_in[14];
    const float* betv = (const float*)d_in[15];
    const float* Wp   = (const float*)d_in[16];
    const float* bp   = (const float*)d_in[17];
    const float* ap   = (const float*)d_in[18];
    const float* gp   = (const float*)d_in[19];
    const float* betp = (const float*)d_in[20];
    float* out = (float*)d_out;

    cudaFuncSetAttribute(gemm_tc<0>, cudaFuncAttributeMaxDynamicSharedMemorySize,
                         GEMM_SMEM_BYTES);
    cudaFuncSetAttribute(gemm_tc<1>, cudaFuncAttributeMaxDynamicSharedMemorySize,
                         GEMM_SMEM_BYTES);

    qkv_kernel<<<dim3(TN, BN), 256>>>(x, Wq, bq, aq, gq, betq,
                                      Wk, bk, ak, gk, betk,
                                      Wv, bv, av, gv, betv);
    gemm_tc<0><<<dim3(TN / 128, TN / 128, HBN), 256, GEMM_SMEM_BYTES>>>();
    softmax_kernel<<<HBN * TN, 256>>>();
    gemm_tc<1><<<dim3(DV / 128, TN / 128, HBN), 256, GEMM_SMEM_BYTES>>>();
    outproj_kernel<<<dim3(TN, BN), 256>>>(x, Wp, bp, ap, gp, betp, out);
}

// round 6
// speedup vs baseline: 1.1385x; 1.0241x over previous
#include <cuda_runtime.h>
#include <cstdint>

// Problem constants
#define HN   4
#define BN   2
#define CN   64
#define TN   2048
#define FN   64
#define HIDN 4
#define VDN  16
#define HBN  8       // H*B
#define DQK  256     // HID*F
#define DV   1024    // VD*F
#define EPSV 1e-5f

// Scratch (static device globals; allocation APIs are banned)
__device__ float g_Q [(size_t)HBN * TN * DQK];   //  16.8 MB (tf32, pre-scaled, [t][d])
__device__ float g_K [(size_t)HBN * TN * DQK];   //  16.8 MB (tf32, [t][d])
__device__ float g_V [(size_t)HBN * TN * DV];    //  67.1 MB (tf32, [t][dv])
__device__ float g_Vt[(size_t)HBN * DV * TN];    //  67.1 MB (tf32, [dv][t])
__device__ float g_S [(size_t)HBN * TN * TN];    // 134.2 MB (fp32 logits -> tf32 probs)
__device__ float g_O [(size_t)HBN * TN * DV];    //  67.1 MB (fp32)

__device__ __forceinline__ float warpSum(float v) {
    #pragma unroll
    for (int s = 16; s > 0; s >>= 1) v += __shfl_down_sync(0xffffffffu, v, s);
    return v;
}
__device__ __forceinline__ float warpMax(float v) {
    #pragma unroll
    for (int s = 16; s > 0; s >>= 1) v = fmaxf(v, __shfl_down_sync(0xffffffffu, v, s));
    return v;
}
__device__ __forceinline__ uint32_t f2tf32(float x) {
    uint32_t u;
    asm("cvt.rna.tf32.f32 %0, %1;" : "=r"(u) : "f"(x));
    return u;
}
__device__ __forceinline__ float tf32f(float x) { return __uint_as_float(f2tf32(x)); }

__device__ __forceinline__ void cpasync16(uint32_t dst, const void* src) {
    asm volatile("cp.async.cg.shared.global [%0], [%1], 16;" :: "r"(dst), "l"(src));
}
__device__ __forceinline__ void ldsm4(uint32_t* r, uint32_t addr) {
    asm volatile("ldmatrix.sync.aligned.m8n8.x4.shared.b16 {%0,%1,%2,%3}, [%4];"
                 : "=r"(r[0]), "=r"(r[1]), "=r"(r[2]), "=r"(r[3]) : "r"(addr));
}

#define MMA_TF32(d, a0, a1, a2, a3, b0, b1)                                   \
    asm volatile(                                                             \
        "mma.sync.aligned.m16n8k8.row.col.f32.tf32.tf32.f32 "                 \
        "{%0,%1,%2,%3}, {%4,%5,%6,%7}, {%8,%9}, {%0,%1,%2,%3};"               \
        : "+f"((d)[0]), "+f"((d)[1]), "+f"((d)[2]), "+f"((d)[3])              \
        : "r"(a0), "r"(a1), "r"(a2), "r"(a3), "r"(b0), "r"(b1))

// ---------------------------------------------------------------------------
// Kernel 1: fused QKV projection + PReLU + LayerNorm over (chan,freq)
// All stores coalesced row-major.
// ---------------------------------------------------------------------------
__global__ __launch_bounds__(256) void qkv_kernel(
    const float* __restrict__ x,
    const float* __restrict__ Wq, const float* __restrict__ bq, const float* __restrict__ aq,
    const float* __restrict__ gq, const float* __restrict__ betq,
    const float* __restrict__ Wk, const float* __restrict__ bk, const float* __restrict__ ak,
    const float* __restrict__ gk, const float* __restrict__ betk,
    const float* __restrict__ Wv, const float* __restrict__ bv, const float* __restrict__ av,
    const float* __restrict__ gv, const float* __restrict__ betv)
{
    __shared__ float xs[CN][FN];
    __shared__ float wt[HN][CN][24];
    __shared__ float rbuf[8][24];
    __shared__ float fin[24];

    const int t = blockIdx.x, b = blockIdx.y;
    const int tid = threadIdx.x;

    for (int i = tid; i < CN * FN; i += 256) {
        int c = i >> 6, f = i & 63;
        xs[c][f] = x[(((size_t)b * CN + c) * TN + t) * FN + f];
    }
    for (int i = tid; i < HN * CN * 24; i += 256) {
        int og = i / (CN * 24);
        int c  = (i / 24) % CN;
        int w  = i % 24;
        float val;
        if (w < 4)      val = Wq[(w * HIDN + og) * CN + c];
        else if (w < 8) val = Wk[((w - 4) * HIDN + og) * CN + c];
        else {
            int j = (w - 8) >> 2, m = (w - 8) & 3;
            val = Wv[(j * VDN + og * 4 + m) * CN + c];
        }
        wt[og][c][w] = val;
    }
    __syncthreads();

    const int f = tid & 63, og = tid >> 6;

    float accq[4], acck[4], accv[16];
    #pragma unroll
    for (int j = 0; j < 4; j++) { accq[j] = bq[j * HIDN + og]; acck[j] = bk[j * HIDN + og]; }
    #pragma unroll
    for (int j = 0; j < 4; j++)
        #pragma unroll
        for (int m = 0; m < 4; m++) accv[j * 4 + m] = bv[j * VDN + og * 4 + m];

    #pragma unroll 4
    for (int c = 0; c < CN; c++) {
        float xv = xs[c][f];
        const float4* wp4 = (const float4*)&wt[og][c][0];
        float w[24];
        *(float4*)&w[0]  = wp4[0];
        *(float4*)&w[4]  = wp4[1];
        *(float4*)&w[8]  = wp4[2];
        *(float4*)&w[12] = wp4[3];
        *(float4*)&w[16] = wp4[4];
        *(float4*)&w[20] = wp4[5];
        #pragma unroll
        for (int q = 0; q < 4; q++)  accq[q] = fmaf(w[q],      xv, accq[q]);
        #pragma unroll
        for (int q = 0; q < 4; q++)  acck[q] = fmaf(w[4 + q],  xv, acck[q]);
        #pragma unroll
        for (int q = 0; q < 16; q++) accv[q] = fmaf(w[8 + q],  xv, accv[q]);
    }

    #pragma unroll
    for (int j = 0; j < 4; j++) {
        float a1 = aq[j], a2 = ak[j];
        accq[j] = accq[j] >= 0.f ? accq[j] : a1 * accq[j];
        acck[j] = acck[j] >= 0.f ? acck[j] : a2 * acck[j];
    }
    #pragma unroll
    for (int j = 0; j < 4; j++) {
        float a3 = av[j];
        #pragma unroll
        for (int m = 0; m < 4; m++) {
            float v = accv[j * 4 + m];
            accv[j * 4 + m] = v >= 0.f ? v : a3 * v;
        }
    }

    float s[12], sq[12];
    #pragma unroll
    for (int j = 0; j < 4; j++) {
        s[j] = accq[j];       sq[j] = accq[j] * accq[j];
        s[4 + j] = acck[j];   sq[4 + j] = acck[j] * acck[j];
        float ps = 0.f, pq = 0.f;
        #pragma unroll
        for (int m = 0; m < 4; m++) { float v = accv[j * 4 + m]; ps += v; pq += v * v; }
        s[8 + j] = ps; sq[8 + j] = pq;
    }
    int lane = tid & 31, wid = tid >> 5;
    #pragma unroll
    for (int q = 0; q < 12; q++) {
        float a = warpSum(s[q]);
        float b2 = warpSum(sq[q]);
        if (lane == 0) { rbuf[wid][q] = a; rbuf[wid][12 + q] = b2; }
    }
    __syncthreads();
    if (tid < 24) {
        float a = 0.f;
        #pragma unroll
        for (int w2 = 0; w2 < 8; w2++) a += rbuf[w2][tid];
        fin[tid] = a;
    }
    __syncthreads();

    const float QSCALE = 0.0625f;  // 1/sqrt(256), folded into Q

    #pragma unroll
    for (int j = 0; j < 4; j++) {
        float mu = fin[j] * (1.f / 256.f);
        float var = fin[12 + j] * (1.f / 256.f) - mu * mu;
        float rs = rsqrtf(var + EPSV);
        int gi = (j * HIDN + og) * FN + f;
        float qv = ((accq[j] - mu) * rs * gq[gi] + betq[gi]) * QSCALE;
        g_Q[(((size_t)(j * BN + b)) * TN + t) * DQK + og * FN + f] = tf32f(qv);

        float muk = fin[4 + j] * (1.f / 256.f);
        float vark = fin[16 + j] * (1.f / 256.f) - muk * muk;
        float rsk = rsqrtf(vark + EPSV);
        float kv = (acck[j] - muk) * rsk * gk[gi] + betk[gi];
        g_K[(((size_t)(j * BN + b)) * TN + t) * DQK + og * FN + f] = tf32f(kv);
    }
    #pragma unroll
    for (int j = 0; j < 4; j++) {
        float mu = fin[8 + j] * (1.f / 1024.f);
        float var = fin[20 + j] * (1.f / 1024.f) - mu * mu;
        float rs = rsqrtf(var + EPSV);
        #pragma unroll
        for (int m = 0; m < 4; m++) {
            int vd = og * 4 + m;
            int gi = (j * VDN + vd) * FN + f;
            float vv = (accv[j * 4 + m] - mu) * rs * gv[gi] + betv[gi];
            g_V[(((size_t)(j * BN + b)) * TN + t) * DV + vd * FN + f] = tf32f(vv);
        }
    }
}

// ---------------------------------------------------------------------------
// Kernel 1b: V transpose  [t][dv] -> [dv][t]   (coalesced both ways)
// ---------------------------------------------------------------------------
__global__ __launch_bounds__(256) void vtrans_kernel()
{
    __shared__ float tile[32][33];
    const int hb = blockIdx.z;
    const int t0 = blockIdx.x * 32, d0 = blockIdx.y * 32;
    const int tx = threadIdx.x & 31, ty = threadIdx.x >> 5;

    #pragma unroll
    for (int p = 0; p < 4; p++) {
        int t = t0 + ty + p * 8;
        tile[ty + p * 8][tx] = g_V[((size_t)hb * TN + t) * DV + d0 + tx];
    }
    __syncthreads();
    #pragma unroll
    for (int p = 0; p < 4; p++) {
        int d = d0 + ty + p * 8;
        g_Vt[((size_t)hb * DV + d) * TN + t0 + tx] = tile[tx][ty + p * 8];
    }
}

// ---------------------------------------------------------------------------
// Kernel 2/4: TF32 tensor-core GEMM v4 — ldmatrix-fed fragments.
//   CTA tile 128x128, BK=16, 256 threads = 8 warps, warp tile 32x64 (4x2),
//   4-stage cp.async pipeline. A smem [m][k] (16k/row, stride 20), B smem
//   [n][k] (same layout). Both fragment sets loaded with ldmatrix.x4.
// MODE 0: S = Q * K^T  (A=g_Q [t][d], B=g_K [t][d]; m=tq, n=tk, k=d)
// MODE 1: O = P * V    (A=g_S [q][t'], B=g_Vt [dv][t']; m=q, n=dv, k=t')
// ---------------------------------------------------------------------------
#define RSTR 20                                    // row stride in floats
#define STAGE_F (128 * RSTR)                       // per-operand stage floats
#define B_BASE_F (4 * STAGE_F)
#define GEMM_SMEM_BYTES (8 * STAGE_F * 4)          // 81920 B

template<int MODE>
__global__ __launch_bounds__(256, 2) void gemm_tc()
{
    constexpr int LDA  = (MODE == 0) ? DQK : TN;
    constexpr int LDB  = (MODE == 0) ? DQK : TN;   // B row stride (n-major global)
    constexpr int LDC  = (MODE == 0) ? TN  : DV;
    constexpr int KTOT = (MODE == 0) ? DQK : TN;
    constexpr int NT   = KTOT / 16;

    extern __shared__ float sm[];

    const int hb = blockIdx.z;
    const float* A = (MODE == 0 ? g_Q : g_S)
                   + (size_t)hb * TN * LDA + (size_t)blockIdx.y * 128 * LDA;
    const float* B = (MODE == 0 ? g_K : g_Vt)
                   + (size_t)hb * (MODE == 0 ? (size_t)TN * DQK : (size_t)DV * TN)
                   + (size_t)blockIdx.x * 128 * LDB;
    float* C = (MODE == 0 ? g_S : g_O)
             + (size_t)hb * TN * LDC + (size_t)blockIdx.y * 128 * LDC + blockIdx.x * 128;

    const int tid = threadIdx.x;
    const int lane = tid & 31, w = tid >> 5;
    const int wm = (w & 3) * 32, wn = (w >> 2) * 64;
    const int r = lane >> 2, cq = lane & 3;

    // loaders: row = tid>>1, two 16B chunks at (tid&1)*8
    const int lrow = tid >> 1, lseg = (tid & 1) * 8;

    const uint32_t smBase = (uint32_t)__cvta_generic_to_shared(sm);

    auto issue = [&](int it, int buf) {
        const float* ap = A + (size_t)lrow * LDA + it * 16 + lseg;
        uint32_t ad = smBase + (uint32_t)(buf * STAGE_F + lrow * RSTR + lseg) * 4u;
        cpasync16(ad, ap);
        cpasync16(ad + 16u, ap + 4);
        const float* bp = B + (size_t)lrow * LDB + it * 16 + lseg;
        uint32_t bd = smBase + (uint32_t)(B_BASE_F + buf * STAGE_F + lrow * RSTR + lseg) * 4u;
        cpasync16(bd, bp);
        cpasync16(bd + 16u, bp + 4);
        asm volatile("cp.async.commit_group;");
    };

    // ldmatrix per-lane base offsets (floats)
    // A x4 tiles (per mi,kk): (m+l&15 rows, kcol = kk + (l>>4)*4)
    const uint32_t a_ln = (uint32_t)((wm + (lane & 15)) * RSTR + (lane >> 4) * 4);
    // B x4 tiles (per ni-pair p,kk): rows wn + p*16 + (l&7) + ((l>>4)<<3), kcol kk + ((l>>3)&1)*4
    const uint32_t b_ln = (uint32_t)((wn + (lane & 7) + ((lane >> 4) << 3)) * RSTR
                                     + (((lane >> 3) & 1) << 2));

    float acc[2][8][4];
    #pragma unroll
    for (int mi = 0; mi < 2; mi++)
        #pragma unroll
        for (int ni = 0; ni < 8; ni++)
            #pragma unroll
            for (int q = 0; q < 4; q++) acc[mi][ni][q] = 0.f;

    issue(0, 0);
    issue(1, 1);
    issue(2, 2);

    for (int it = 0; it < NT; ++it) {
        if (it + 2 < NT)      asm volatile("cp.async.wait_group 2;");
        else if (it + 1 < NT) asm volatile("cp.async.wait_group 1;");
        else                  asm volatile("cp.async.wait_group 0;");
        __syncthreads();

        if (it + 3 < NT) issue(it + 3, (it + 3) & 3);

        const uint32_t aBase = smBase + (uint32_t)((it & 3) * STAGE_F) * 4u;
        const uint32_t bBase = smBase + (uint32_t)(B_BASE_F + (it & 3) * STAGE_F) * 4u;

        #pragma unroll
        for (int kk = 0; kk < 16; kk += 8) {
            uint32_t af[2][4];
            #pragma unroll
            for (int mi = 0; mi < 2; mi++)
                ldsm4(af[mi], aBase + (a_ln + mi * 16 * RSTR + kk) * 4u);
            uint32_t bf[4][4];
            #pragma unroll
            for (int p = 0; p < 4; p++)
                ldsm4(bf[p], bBase + (b_ln + p * 16 * RSTR + kk) * 4u);
            #pragma unroll
            for (int mi = 0; mi < 2; mi++)
                #pragma unroll
                for (int p = 0; p < 4; p++) {
                    MMA_TF32(acc[mi][2 * p],     af[mi][0], af[mi][1], af[mi][2], af[mi][3],
                             bf[p][0], bf[p][1]);
                    MMA_TF32(acc[mi][2 * p + 1], af[mi][0], af[mi][1], af[mi][2], af[mi][3],
                             bf[p][2], bf[p][3]);
                }
        }
        __syncthreads();
    }

    #pragma unroll
    for (int mi = 0; mi < 2; mi++) {
        const int row0 = wm + mi * 16 + r;
        #pragma unroll
        for (int ni = 0; ni < 8; ni++) {
            const int col = wn + ni * 8 + cq * 2;
            float2 v0 = make_float2(acc[mi][ni][0], acc[mi][ni][1]);
            float2 v1 = make_float2(acc[mi][ni][2], acc[mi][ni][3]);
            *(float2*)&C[(size_t)row0 * LDC + col]       = v0;
            *(float2*)&C[(size_t)(row0 + 8) * LDC + col] = v1;
        }
    }
}

// ---------------------------------------------------------------------------
// Kernel 3: row softmax (one read + one write), output rounded to tf32
// ---------------------------------------------------------------------------
__global__ __launch_bounds__(256) void softmax_kernel()
{
    const size_t row = blockIdx.x;
    float* p = g_S + row * TN;
    const int tid = threadIdx.x;
    const int lane = tid & 31, wid = tid >> 5;
    __shared__ float red[8];
    __shared__ float bmax, bsum;

    float v[8];
    float m = -1e30f;
    #pragma unroll
    for (int j = 0; j < 8; j++) { v[j] = p[tid + j * 256]; m = fmaxf(m, v[j]); }
    m = warpMax(m);
    if (lane == 0) red[wid] = m;
    __syncthreads();
    if (tid == 0) {
        float mm = red[0];
        #pragma unroll
        for (int w = 1; w < 8; w++) mm = fmaxf(mm, red[w]);
        bmax = mm;
    }
    __syncthreads();
    float M = bmax;
    float sum = 0.f;
    #pragma unroll
    for (int j = 0; j < 8; j++) { v[j] = __expf(v[j] - M); sum += v[j]; }
    sum = warpSum(sum);
    if (lane == 0) red[wid] = sum;
    __syncthreads();
    if (tid == 0) {
        float ss = 0.f;
        #pragma unroll
        for (int w = 0; w < 8; w++) ss += red[w];
        bsum = ss;
    }
    __syncthreads();
    float r = 1.f / bsum;
    #pragma unroll
    for (int j = 0; j < 8; j++) p[tid + j * 256] = tf32f(v[j] * r);
}

// ---------------------------------------------------------------------------
// Kernel 5: out = LN(PReLU(Wp @ concat(O) + bp)) + x   per (b,t)
// ---------------------------------------------------------------------------
__global__ __launch_bounds__(256) void outproj_kernel(
    const float* __restrict__ x, const float* __restrict__ Wp, const float* __restrict__ bp,
    const float* __restrict__ ap, const float* __restrict__ gp, const float* __restrict__ betp,
    float* __restrict__ out)
{
    __shared__ float Oc[CN][FN];
    __shared__ float wt[4][CN][16];
    __shared__ float rbuf[8][2];
    __shared__ float fin2[2];

    const int t = blockIdx.x, b = blockIdx.y;
    const int tid = threadIdx.x;

    for (int i = tid; i < CN * FN; i += 256) {
        int c = i >> 6, f = i & 63;
        int h = c >> 4, vd = c & 15;
        Oc[c][f] = g_O[(((size_t)(h * BN + b)) * TN + t) * DV + vd * FN + f];
    }
    for (int i = tid; i < 4 * CN * 16; i += 256) {
        int og = i / (CN * 16), c = (i >> 4) % CN, m = i & 15;
        wt[og][c][m] = Wp[(og * 16 + m) * CN + c];
    }
    __syncthreads();

    const int f = tid & 63, og = tid >> 6;
    float acc[16];
    #pragma unroll
    for (int m = 0; m < 16; m++) acc[m] = bp[og * 16 + m];

    #pragma unroll 4
    for (int c = 0; c < CN; c++) {
        float xv = Oc[c][f];
        const float4* wp4 = (const float4*)&wt[og][c][0];
        float w[16];
        *(float4*)&w[0]  = wp4[0];
        *(float4*)&w[4]  = wp4[1];
        *(float4*)&w[8]  = wp4[2];
        *(float4*)&w[12] = wp4[3];
        #pragma unroll
        for (int m = 0; m < 16; m++) acc[m] = fmaf(w[m], xv, acc[m]);
    }

    float a = ap[0];
    float ps = 0.f, pq = 0.f;
    #pragma unroll
    for (int m = 0; m < 16; m++) {
        float v = acc[m];
        v = v >= 0.f ? v : a * v;
        acc[m] = v;
        ps += v; pq += v * v;
    }
    int lane = tid & 31, wid = tid >> 5;
    ps = warpSum(ps); pq = warpSum(pq);
    if (lane == 0) { rbuf[wid][0] = ps; rbuf[wid][1] = pq; }
    __syncthreads();
    if (tid == 0) {
        float s0 = 0.f, s1 = 0.f;
        #pragma unroll
        for (int w = 0; w < 8; w++) { s0 += rbuf[w][0]; s1 += rbuf[w][1]; }
        fin2[0] = s0; fin2[1] = s1;
    }
    __syncthreads();
    float mu = fin2[0] * (1.f / 4096.f);
    float var = fin2[1] * (1.f / 4096.f) - mu * mu;
    float rs = rsqrtf(var + EPSV);

    #pragma unroll
    for (int m = 0; m < 16; m++) {
        int o = og * 16 + m;
        float v = (acc[m] - mu) * rs * gp[o * FN + f] + betp[o * FN + f];
        size_t idx = (((size_t)b * CN + o) * TN + t) * FN + f;
        out[idx] = v + x[idx];
    }
}

// ---------------------------------------------------------------------------
extern "C" void kernel_launch(void* const* d_in, const int* in_sizes, int n_in,
                              void* d_out, int out_size)
{
    const float* x    = (const float*)d_in[0];
    const float* Wq   = (const float*)d_in[1];
    const float* bq   = (const float*)d_in[2];
    const float* aq   = (const float*)d_in[3];
    const float* gq   = (const float*)d_in[4];
    const float* betq = (const float*)d_in[5];
    const float* Wk   = (const float*)d_in[6];
    const float* bk   = (const float*)d_in[7];
    const float* ak   = (const float*)d_in[8];
    const float* gk   = (const float*)d_in[9];
    const float* betk = (const float*)d_in[10];
    const float* Wv   = (const float*)d_in[11];
    const float* bv   = (const float*)d_in[12];
    const float* av   = (const float*)d_in[13];
    const float* gv   = (const float*)d_in[14];
    const float* betv = (const float*)d_in[15];
    const float* Wp   = (const float*)d_in[16];
    const float* bp   = (const float*)d_in[17];
    const float* ap   = (const float*)d_in[18];
    const float* gp   = (const float*)d_in[19];
    const float* betp = (const float*)d_in[20];
    float* out = (float*)d_out;

    cudaFuncSetAttribute(gemm_tc<0>, cudaFuncAttributeMaxDynamicSharedMemorySize,
                         GEMM_SMEM_BYTES);
    cudaFuncSetAttribute(gemm_tc<1>, cudaFuncAttributeMaxDynamicSharedMemorySize,
                         GEMM_SMEM_BYTES);

    qkv_kernel<<<dim3(TN, BN), 256>>>(x, Wq, bq, aq, gq, betq,
                                      Wk, bk, ak, gk, betk,
                                      Wv, bv, av, gv, betv);
    vtrans_kernel<<<dim3(TN / 32, DV / 32, HBN), 256>>>();
    gemm_tc<0><<<dim3(TN / 128, TN / 128, HBN), 256, GEMM_SMEM_BYTES>>>();
    softmax_kernel<<<HBN * TN, 256>>>();
    gemm_tc<1><<<dim3(DV / 128, TN / 128, HBN), 256, GEMM_SMEM_BYTES>>>();
    outproj_kernel<<<dim3(TN, BN), 256>>>(x, Wp, bp, ap, gp, betp, out);
}

// round 7
// speedup vs baseline: 1.6271x; 1.4292x over previous
#include <cuda_runtime.h>
#include <cuda_fp16.h>
#include <cstdint>

// Problem constants
#define HN   4
#define BN   2
#define CN   64
#define TN   2048
#define FN   64
#define HIDN 4
#define VDN  16
#define HBN  8       // H*B
#define DQK  256     // HID*F
#define DV   1024    // VD*F
#define EPSV 1e-5f

// Scratch (static device globals; allocation APIs are banned)
__device__ __half g_Qh [(size_t)HBN * TN * DQK];  //  8.4 MB (fp16, pre-scaled, [t][d])
__device__ __half g_Kh [(size_t)HBN * TN * DQK];  //  8.4 MB (fp16, [t][d])
__device__ __half g_Vh [(size_t)HBN * TN * DV];   // 33.5 MB (fp16, [t][dv])
__device__ __half g_Vth[(size_t)HBN * DV * TN];   // 33.5 MB (fp16, [dv][t])
__device__ float  g_S  [(size_t)HBN * TN * TN];   // 134 MB (fp32 logits)
__device__ __half g_P  [(size_t)HBN * TN * TN];   //  67 MB (fp16 probs)
__device__ float  g_O  [(size_t)HBN * TN * DV];   //  67 MB (fp32)

__device__ __forceinline__ float warpSum(float v) {
    #pragma unroll
    for (int s = 16; s > 0; s >>= 1) v += __shfl_down_sync(0xffffffffu, v, s);
    return v;
}
__device__ __forceinline__ float warpMax(float v) {
    #pragma unroll
    for (int s = 16; s > 0; s >>= 1) v = fmaxf(v, __shfl_down_sync(0xffffffffu, v, s));
    return v;
}
__device__ __forceinline__ void cpasync16(uint32_t dst, const void* src) {
    asm volatile("cp.async.cg.shared.global [%0], [%1], 16;" :: "r"(dst), "l"(src));
}
__device__ __forceinline__ void ldsm4(uint32_t* r, uint32_t addr) {
    asm volatile("ldmatrix.sync.aligned.m8n8.x4.shared.b16 {%0,%1,%2,%3}, [%4];"
                 : "=r"(r[0]), "=r"(r[1]), "=r"(r[2]), "=r"(r[3]) : "r"(addr));
}

#define MMA_F16(d, a, b0, b1)                                                 \
    asm volatile(                                                             \
        "mma.sync.aligned.m16n8k16.row.col.f32.f16.f16.f32 "                  \
        "{%0,%1,%2,%3}, {%4,%5,%6,%7}, {%8,%9}, {%0,%1,%2,%3};"               \
        : "+f"((d)[0]), "+f"((d)[1]), "+f"((d)[2]), "+f"((d)[3])              \
        : "r"((a)[0]), "r"((a)[1]), "r"((a)[2]), "r"((a)[3]),                 \
          "r"(b0), "r"(b1))

// ---------------------------------------------------------------------------
// Kernel 1: fused QKV projection + PReLU + LayerNorm over (chan,freq)
// Outputs fp16, all stores coalesced row-major.
// ---------------------------------------------------------------------------
__global__ __launch_bounds__(256) void qkv_kernel(
    const float* __restrict__ x,
    const float* __restrict__ Wq, const float* __restrict__ bq, const float* __restrict__ aq,
    const float* __restrict__ gq, const float* __restrict__ betq,
    const float* __restrict__ Wk, const float* __restrict__ bk, const float* __restrict__ ak,
    const float* __restrict__ gk, const float* __restrict__ betk,
    const float* __restrict__ Wv, const float* __restrict__ bv, const float* __restrict__ av,
    const float* __restrict__ gv, const float* __restrict__ betv)
{
    __shared__ float xs[CN][FN];
    __shared__ float wt[HN][CN][24];
    __shared__ float rbuf[8][24];
    __shared__ float fin[24];

    const int t = blockIdx.x, b = blockIdx.y;
    const int tid = threadIdx.x;

    for (int i = tid; i < CN * FN; i += 256) {
        int c = i >> 6, f = i & 63;
        xs[c][f] = x[(((size_t)b * CN + c) * TN + t) * FN + f];
    }
    for (int i = tid; i < HN * CN * 24; i += 256) {
        int og = i / (CN * 24);
        int c  = (i / 24) % CN;
        int w  = i % 24;
        float val;
        if (w < 4)      val = Wq[(w * HIDN + og) * CN + c];
        else if (w < 8) val = Wk[((w - 4) * HIDN + og) * CN + c];
        else {
            int j = (w - 8) >> 2, m = (w - 8) & 3;
            val = Wv[(j * VDN + og * 4 + m) * CN + c];
        }
        wt[og][c][w] = val;
    }
    __syncthreads();

    const int f = tid & 63, og = tid >> 6;

    float accq[4], acck[4], accv[16];
    #pragma unroll
    for (int j = 0; j < 4; j++) { accq[j] = bq[j * HIDN + og]; acck[j] = bk[j * HIDN + og]; }
    #pragma unroll
    for (int j = 0; j < 4; j++)
        #pragma unroll
        for (int m = 0; m < 4; m++) accv[j * 4 + m] = bv[j * VDN + og * 4 + m];

    #pragma unroll 4
    for (int c = 0; c < CN; c++) {
        float xv = xs[c][f];
        const float4* wp4 = (const float4*)&wt[og][c][0];
        float w[24];
        *(float4*)&w[0]  = wp4[0];
        *(float4*)&w[4]  = wp4[1];
        *(float4*)&w[8]  = wp4[2];
        *(float4*)&w[12] = wp4[3];
        *(float4*)&w[16] = wp4[4];
        *(float4*)&w[20] = wp4[5];
        #pragma unroll
        for (int q = 0; q < 4; q++)  accq[q] = fmaf(w[q],      xv, accq[q]);
        #pragma unroll
        for (int q = 0; q < 4; q++)  acck[q] = fmaf(w[4 + q],  xv, acck[q]);
        #pragma unroll
        for (int q = 0; q < 16; q++) accv[q] = fmaf(w[8 + q],  xv, accv[q]);
    }

    #pragma unroll
    for (int j = 0; j < 4; j++) {
        float a1 = aq[j], a2 = ak[j];
        accq[j] = accq[j] >= 0.f ? accq[j] : a1 * accq[j];
        acck[j] = acck[j] >= 0.f ? acck[j] : a2 * acck[j];
    }
    #pragma unroll
    for (int j = 0; j < 4; j++) {
        float a3 = av[j];
        #pragma unroll
        for (int m = 0; m < 4; m++) {
            float v = accv[j * 4 + m];
            accv[j * 4 + m] = v >= 0.f ? v : a3 * v;
        }
    }

    float s[12], sq[12];
    #pragma unroll
    for (int j = 0; j < 4; j++) {
        s[j] = accq[j];       sq[j] = accq[j] * accq[j];
        s[4 + j] = acck[j];   sq[4 + j] = acck[j] * acck[j];
        float ps = 0.f, pq = 0.f;
        #pragma unroll
        for (int m = 0; m < 4; m++) { float v = accv[j * 4 + m]; ps += v; pq += v * v; }
        s[8 + j] = ps; sq[8 + j] = pq;
    }
    int lane = tid & 31, wid = tid >> 5;
    #pragma unroll
    for (int q = 0; q < 12; q++) {
        float a = warpSum(s[q]);
        float b2 = warpSum(sq[q]);
        if (lane == 0) { rbuf[wid][q] = a; rbuf[wid][12 + q] = b2; }
    }
    __syncthreads();
    if (tid < 24) {
        float a = 0.f;
        #pragma unroll
        for (int w2 = 0; w2 < 8; w2++) a += rbuf[w2][tid];
        fin[tid] = a;
    }
    __syncthreads();

    const float QSCALE = 0.0625f;  // 1/sqrt(256), folded into Q

    #pragma unroll
    for (int j = 0; j < 4; j++) {
        float mu = fin[j] * (1.f / 256.f);
        float var = fin[12 + j] * (1.f / 256.f) - mu * mu;
        float rs = rsqrtf(var + EPSV);
        int gi = (j * HIDN + og) * FN + f;
        float qv = ((accq[j] - mu) * rs * gq[gi] + betq[gi]) * QSCALE;
        g_Qh[(((size_t)(j * BN + b)) * TN + t) * DQK + og * FN + f] = __float2half_rn(qv);

        float muk = fin[4 + j] * (1.f / 256.f);
        float vark = fin[16 + j] * (1.f / 256.f) - muk * muk;
        float rsk = rsqrtf(vark + EPSV);
        float kv = (acck[j] - muk) * rsk * gk[gi] + betk[gi];
        g_Kh[(((size_t)(j * BN + b)) * TN + t) * DQK + og * FN + f] = __float2half_rn(kv);
    }
    #pragma unroll
    for (int j = 0; j < 4; j++) {
        float mu = fin[8 + j] * (1.f / 1024.f);
        float var = fin[20 + j] * (1.f / 1024.f) - mu * mu;
        float rs = rsqrtf(var + EPSV);
        #pragma unroll
        for (int m = 0; m < 4; m++) {
            int vd = og * 4 + m;
            int gi = (j * VDN + vd) * FN + f;
            float vv = (accv[j * 4 + m] - mu) * rs * gv[gi] + betv[gi];
            g_Vh[(((size_t)(j * BN + b)) * TN + t) * DV + vd * FN + f] = __float2half_rn(vv);
        }
    }
}

// ---------------------------------------------------------------------------
// Kernel 1b: V transpose  [t][dv] -> [dv][t]  (fp16)
// ---------------------------------------------------------------------------
__global__ __launch_bounds__(256) void vtrans_kernel()
{
    __shared__ __half tile[32][34];
    const int hb = blockIdx.z;
    const int t0 = blockIdx.x * 32, d0 = blockIdx.y * 32;
    const int tx = threadIdx.x & 31, ty = threadIdx.x >> 5;

    #pragma unroll
    for (int p = 0; p < 4; p++) {
        int t = t0 + ty + p * 8;
        tile[ty + p * 8][tx] = g_Vh[((size_t)hb * TN + t) * DV + d0 + tx];
    }
    __syncthreads();
    #pragma unroll
    for (int p = 0; p < 4; p++) {
        int d = d0 + ty + p * 8;
        g_Vth[((size_t)hb * DV + d) * TN + t0 + tx] = tile[tx][ty + p * 8];
    }
}

// ---------------------------------------------------------------------------
// Kernel 2/4: FP16 tensor-core GEMM (f32 accum) — ldmatrix-fed m16n8k16.
//   CTA tile 128x128, BK=32, 256 threads = 8 warps, warp tile 32x64 (4x2),
//   4-stage cp.async pipeline. A smem [m][k], B smem [n][k], 32 halves/row,
//   row stride 40 halves (80B -> conflict-free ldmatrix).
// MODE 0: S = Q * K^T  (A=g_Qh [t][d], B=g_Kh [t][d]; m=tq, n=tk, k=d)
// MODE 1: O = P * V    (A=g_P [q][t'], B=g_Vth [dv][t']; m=q, n=dv, k=t')
// ---------------------------------------------------------------------------
#define RSTR 40                                     // row stride in halves
#define STAGE_H (128 * RSTR)                        // per-operand stage halves
#define B_BASE_H (4 * STAGE_H)
#define GEMM_SMEM_BYTES (8 * STAGE_H * 2)           // 81920 B

template<int MODE>
__global__ __launch_bounds__(256, 2) void gemm_tc()
{
    constexpr int LDA  = (MODE == 0) ? DQK : TN;
    constexpr int LDB  = (MODE == 0) ? DQK : TN;
    constexpr int LDC  = (MODE == 0) ? TN  : DV;
    constexpr int KTOT = (MODE == 0) ? DQK : TN;
    constexpr int NT   = KTOT / 32;

    extern __shared__ __half sm[];

    const int hb = blockIdx.z;
    const __half* A = (MODE == 0 ? g_Qh : g_P)
                    + (size_t)hb * TN * LDA + (size_t)blockIdx.y * 128 * LDA;
    const __half* B = (MODE == 0 ? g_Kh : g_Vth)
                    + (size_t)hb * (MODE == 0 ? (size_t)TN * DQK : (size_t)DV * TN)
                    + (size_t)blockIdx.x * 128 * LDB;
    float* C = (MODE == 0 ? g_S : g_O)
             + (size_t)hb * TN * LDC + (size_t)blockIdx.y * 128 * LDC + blockIdx.x * 128;

    const int tid = threadIdx.x;
    const int lane = tid & 31, w = tid >> 5;
    const int wm = (w & 3) * 32, wn = (w >> 2) * 64;
    const int r = lane >> 2, cq = lane & 3;

    // loaders: row = tid>>1, 16-half (32B) chunk at (tid&1)*16
    const int lrow = tid >> 1, lseg = (tid & 1) * 16;

    const uint32_t smBase = (uint32_t)__cvta_generic_to_shared(sm);

    auto issue = [&](int it, int buf) {
        const __half* ap = A + (size_t)lrow * LDA + it * 32 + lseg;
        uint32_t ad = smBase + (uint32_t)(buf * STAGE_H + lrow * RSTR + lseg) * 2u;
        cpasync16(ad, ap);
        cpasync16(ad + 16u, ap + 8);
        const __half* bp = B + (size_t)lrow * LDB + it * 32 + lseg;
        uint32_t bd = smBase + (uint32_t)(B_BASE_H + buf * STAGE_H + lrow * RSTR + lseg) * 2u;
        cpasync16(bd, bp);
        cpasync16(bd + 16u, bp + 8);
        asm volatile("cp.async.commit_group;");
    };

    // ldmatrix per-lane base offsets (halves)
    // A x4 (per mi,kk): rows wm+mi*16+(l&15), col halves kk + (l>>4)*8
    const uint32_t a_ln = (uint32_t)((wm + (lane & 15)) * RSTR + (lane >> 4) * 8);
    // B x4 (per p,kk): rows wn + p*16 + (l&7) + ((l>>4)<<3), col kk + ((l>>3)&1)*8
    const uint32_t b_ln = (uint32_t)((wn + (lane & 7) + ((lane >> 4) << 3)) * RSTR
                                     + (((lane >> 3) & 1) << 3));

    float acc[2][8][4];
    #pragma unroll
    for (int mi = 0; mi < 2; mi++)
        #pragma unroll
        for (int ni = 0; ni < 8; ni++)
            #pragma unroll
            for (int q = 0; q < 4; q++) acc[mi][ni][q] = 0.f;

    issue(0, 0);
    issue(1, 1);
    issue(2, 2);

    for (int it = 0; it < NT; ++it) {
        if (it + 2 < NT)      asm volatile("cp.async.wait_group 2;");
        else if (it + 1 < NT) asm volatile("cp.async.wait_group 1;");
        else                  asm volatile("cp.async.wait_group 0;");
        __syncthreads();

        if (it + 3 < NT) issue(it + 3, (it + 3) & 3);

        const uint32_t aBase = smBase + (uint32_t)((it & 3) * STAGE_H) * 2u;
        const uint32_t bBase = smBase + (uint32_t)(B_BASE_H + (it & 3) * STAGE_H) * 2u;

        #pragma unroll
        for (int kk = 0; kk < 32; kk += 16) {
            uint32_t af[2][4];
            #pragma unroll
            for (int mi = 0; mi < 2; mi++)
                ldsm4(af[mi], aBase + (a_ln + mi * 16 * RSTR + kk) * 2u);
            uint32_t bf[4][4];
            #pragma unroll
            for (int p = 0; p < 4; p++)
                ldsm4(bf[p], bBase + (b_ln + p * 16 * RSTR + kk) * 2u);
            #pragma unroll
            for (int mi = 0; mi < 2; mi++)
                #pragma unroll
                for (int p = 0; p < 4; p++) {
                    MMA_F16(acc[mi][2 * p],     af[mi], bf[p][0], bf[p][1]);
                    MMA_F16(acc[mi][2 * p + 1], af[mi], bf[p][2], bf[p][3]);
                }
        }
        __syncthreads();
    }

    #pragma unroll
    for (int mi = 0; mi < 2; mi++) {
        const int row0 = wm + mi * 16 + r;
        #pragma unroll
        for (int ni = 0; ni < 8; ni++) {
            const int col = wn + ni * 8 + cq * 2;
            float2 v0 = make_float2(acc[mi][ni][0], acc[mi][ni][1]);
            float2 v1 = make_float2(acc[mi][ni][2], acc[mi][ni][3]);
            *(float2*)&C[(size_t)row0 * LDC + col]       = v0;
            *(float2*)&C[(size_t)(row0 + 8) * LDC + col] = v1;
        }
    }
}

// ---------------------------------------------------------------------------
// Kernel 3: row softmax; reads fp32 logits, writes fp16 probs
// ---------------------------------------------------------------------------
__global__ __launch_bounds__(256) void softmax_kernel()
{
    const size_t row = blockIdx.x;
    const float* p = g_S + row * TN;
    __half* po = g_P + row * TN;
    const int tid = threadIdx.x;
    const int lane = tid & 31, wid = tid >> 5;
    __shared__ float red[8];
    __shared__ float bmax, bsum;

    float v[8];
    float m = -1e30f;
    #pragma unroll
    for (int j = 0; j < 8; j++) { v[j] = p[tid + j * 256]; m = fmaxf(m, v[j]); }
    m = warpMax(m);
    if (lane == 0) red[wid] = m;
    __syncthreads();
    if (tid == 0) {
        float mm = red[0];
        #pragma unroll
        for (int w = 1; w < 8; w++) mm = fmaxf(mm, red[w]);
        bmax = mm;
    }
    __syncthreads();
    float M = bmax;
    float sum = 0.f;
    #pragma unroll
    for (int j = 0; j < 8; j++) { v[j] = __expf(v[j] - M); sum += v[j]; }
    sum = warpSum(sum);
    if (lane == 0) red[wid] = sum;
    __syncthreads();
    if (tid == 0) {
        float ss = 0.f;
        #pragma unroll
        for (int w = 0; w < 8; w++) ss += red[w];
        bsum = ss;
    }
    __syncthreads();
    float r = 1.f / bsum;
    #pragma unroll
    for (int j = 0; j < 8; j++) po[tid + j * 256] = __float2half_rn(v[j] * r);
}

// ---------------------------------------------------------------------------
// Kernel 5: out = LN(PReLU(Wp @ concat(O) + bp)) + x   per (b,t)
// ---------------------------------------------------------------------------
__global__ __launch_bounds__(256) void outproj_kernel(
    const float* __restrict__ x, const float* __restrict__ Wp, const float* __restrict__ bp,
    const float* __restrict__ ap, const float* __restrict__ gp, const float* __restrict__ betp,
    float* __restrict__ out)
{
    __shared__ float Oc[CN][FN];
    __shared__ float wt[4][CN][16];
    __shared__ float rbuf[8][2];
    __shared__ float fin2[2];

    const int t = blockIdx.x, b = blockIdx.y;
    const int tid = threadIdx.x;

    for (int i = tid; i < CN * FN; i += 256) {
        int c = i >> 6, f = i & 63;
        int h = c >> 4, vd = c & 15;
        Oc[c][f] = g_O[(((size_t)(h * BN + b)) * TN + t) * DV + vd * FN + f];
    }
    for (int i = tid; i < 4 * CN * 16; i += 256) {
        int og = i / (CN * 16), c = (i >> 4) % CN, m = i & 15;
        wt[og][c][m] = Wp[(og * 16 + m) * CN + c];
    }
    __syncthreads();

    const int f = tid & 63, og = tid >> 6;
    float acc[16];
    #pragma unroll
    for (int m = 0; m < 16; m++) acc[m] = bp[og * 16 + m];

    #pragma unroll 4
    for (int c = 0; c < CN; c++) {
        float xv = Oc[c][f];
        const float4* wp4 = (const float4*)&wt[og][c][0];
        float w[16];
        *(float4*)&w[0]  = wp4[0];
        *(float4*)&w[4]  = wp4[1];
        *(float4*)&w[8]  = wp4[2];
        *(float4*)&w[12] = wp4[3];
        #pragma unroll
        for (int m = 0; m < 16; m++) acc[m] = fmaf(w[m], xv, acc[m]);
    }

    float a = ap[0];
    float ps = 0.f, pq = 0.f;
    #pragma unroll
    for (int m = 0; m < 16; m++) {
        float v = acc[m];
        v = v >= 0.f ? v : a * v;
        acc[m] = v;
        ps += v; pq += v * v;
    }
    int lane = tid & 31, wid = tid >> 5;
    ps = warpSum(ps); pq = warpSum(pq);
    if (lane == 0) { rbuf[wid][0] = ps; rbuf[wid][1] = pq; }
    __syncthreads();
    if (tid == 0) {
        float s0 = 0.f, s1 = 0.f;
        #pragma unroll
        for (int w = 0; w < 8; w++) { s0 += rbuf[w][0]; s1 += rbuf[w][1]; }
        fin2[0] = s0; fin2[1] = s1;
    }
    __syncthreads();
    float mu = fin2[0] * (1.f / 4096.f);
    float var = fin2[1] * (1.f / 4096.f) - mu * mu;
    float rs = rsqrtf(var + EPSV);

    #pragma unroll
    for (int m = 0; m < 16; m++) {
        int o = og * 16 + m;
        float v = (acc[m] - mu) * rs * gp[o * FN + f] + betp[o * FN + f];
        size_t idx = (((size_t)b * CN + o) * TN + t) * FN + f;
        out[idx] = v + x[idx];
    }
}

// ---------------------------------------------------------------------------
extern "C" void kernel_launch(void* const* d_in, const int* in_sizes, int n_in,
                              void* d_out, int out_size)
{
    const float* x    = (const float*)d_in[0];
    const float* Wq   = (const float*)d_in[1];
    const float* bq   = (const float*)d_in[2];
    const float* aq   = (const float*)d_in[3];
    const float* gq   = (const float*)d_in[4];
    const float* betq = (const float*)d_in[5];
    const float* Wk   = (const float*)d_in[6];
    const float* bk   = (const float*)d_in[7];
    const float* ak   = (const float*)d_in[8];
    const float* gk   = (const float*)d_in[9];
    const float* betk = (const float*)d_in[10];
    const float* Wv   = (const float*)d_in[11];
    const float* bv   = (const float*)d_in[12];
    const float* av   = (const float*)d_in[13];
    const float* gv   = (const float*)d_in[14];
    const float* betv = (const float*)d_in[15];
    const float* Wp   = (const float*)d_in[16];
    const float* bp   = (const float*)d_in[17];
    const float* ap   = (const float*)d_in[18];
    const float* gp   = (const float*)d_in[19];
    const float* betp = (const float*)d_in[20];
    float* out = (float*)d_out;

    cudaFuncSetAttribute(gemm_tc<0>, cudaFuncAttributeMaxDynamicSharedMemorySize,
                         GEMM_SMEM_BYTES);
    cudaFuncSetAttribute(gemm_tc<1>, cudaFuncAttributeMaxDynamicSharedMemorySize,
                         GEMM_SMEM_BYTES);

    qkv_kernel<<<dim3(TN, BN), 256>>>(x, Wq, bq, aq, gq, betq,
                                      Wk, bk, ak, gk, betk,
                                      Wv, bv, av, gv, betv);
    vtrans_kernel<<<dim3(TN / 32, DV / 32, HBN), 256>>>();
    gemm_tc<0><<<dim3(TN / 128, TN / 128, HBN), 256, GEMM_SMEM_BYTES>>>();
    softmax_kernel<<<HBN * TN, 256>>>();
    gemm_tc<1><<<dim3(DV / 128, TN / 128, HBN), 256, GEMM_SMEM_BYTES>>>();
    outproj_kernel<<<dim3(TN, BN), 256>>>(x, Wp, bp, ap, gp, betp, out);
}